// round 9
// baseline (speedup 1.0000x reference)
#include <cuda_runtime.h>

#define NS 10
#define ND 32
#define NL 4
#define NB 1024

typedef unsigned long long u64;

// ---- packed f32x2 helpers (sm_103a) ----
__device__ __forceinline__ u64 ffma2(u64 a, u64 b, u64 c) {
    u64 d;
    asm("fma.rn.f32x2 %0, %1, %2, %3;" : "=l"(d) : "l"(a), "l"(b), "l"(c));
    return d;
}
__device__ __forceinline__ u64 fadd2(u64 a, u64 b) {
    u64 d;
    asm("add.rn.f32x2 %0, %1, %2;" : "=l"(d) : "l"(a), "l"(b));
    return d;
}
__device__ __forceinline__ u64 pack2(float lo, float hi) {
    u64 d;
    asm("mov.b64 %0, {%1, %2};" : "=l"(d) : "f"(lo), "f"(hi));
    return d;
}
__device__ __forceinline__ float hsum2(u64 v) {
    float lo, hi;
    asm("mov.b64 {%0, %1}, %2;" : "=f"(lo), "=f"(hi) : "l"(v));
    return lo + hi;
}

__global__ __launch_bounds__(128, 6)
void dendrite_kernel(const float* __restrict__ x,
                     const float* __restrict__ k,
                     const float* __restrict__ w,
                     const float* __restrict__ q,
                     const float* __restrict__ dend_w,
                     const float* __restrict__ dend_b,
                     const float* __restrict__ lin_w,
                     const float* __restrict__ lin_b,
                     const float* __restrict__ final_w,
                     const float* __restrict__ final_b,
                     const float* __restrict__ ks,
                     float* __restrict__ out)
{
    // dend_w per-layer, zero at v=0 so the excluded empty subset drops out
    __shared__ __align__(16) float sdw[NL * 1024];
    __shared__ float sred[NL];

    const int tid = threadIdx.x;
    const int l   = tid >> 5;        // warp == layer
    const int d   = tid & 31;        // lane == dendrite
    const int b   = blockIdx.x;      // one batch element per block

    // stage dend_w (32 independent LDG per thread, MLP-unrolled)
    #pragma unroll
    for (int it = 0; it < 32; ++it) {
        int i  = tid + it * 128;
        int ll = i >> 10, v = i & 1023;
        sdw[i] = v ? dend_w[ll * 1023 + v - 1] : 0.0f;
    }

    // ---- setup: s_i = sigmoid(k*(w*x - q)) ----
    const int base = (l * ND + d) * NS;
    float s[NS];
    #pragma unroll
    for (int i = 0; i < NS; ++i) {
        float z = k[base + i] * (w[base + i] * x[b * NS + i] - q[base + i]);
        s[i] = 1.0f / (1.0f + __expf(-z));
    }

    // subset products of low-5 mask bits (bit p of lo -> s[9-p])
    u64 Pp[16];
    {
        float Plo[32];
        Plo[0] = 1.0f;
        #pragma unroll
        for (int bit = 0; bit < 5; ++bit) {
            const float sv = s[9 - bit];
            #pragma unroll
            for (int u = 0; u < (1 << bit); ++u)
                Plo[(1 << bit) + u] = Plo[u] * sv;
        }
        #pragma unroll
        for (int u = 0; u < 16; ++u) Pp[u] = pack2(Plo[2 * u], Plo[2 * u + 1]);
    }

    // h-tree factors (bit p of h -> s[4-p]), duplicated into both f32x2 lanes
    u64 sHp[5];
    #pragma unroll
    for (int p = 0; p < 5; ++p) sHp[p] = pack2(s[4 - p], s[4 - p]);

    __syncthreads();

    // ---- mainloop: g_h = sum_lo sdw[32h+lo]*Plo[lo]; res = sum_h Phi[h] g_h.
    // The Horner tree runs on the packed (lo,hi) partial pair; one hsum at end.
    const ulonglong2* __restrict__ row =
        reinterpret_cast<const ulonglong2*>(sdw + (l << 10));

    u64 lvl[5];
    u64 res2 = 0ULL;

    ulonglong2 c0 = row[0], c1 = row[1], c2 = row[2], c3 = row[3];

    #pragma unroll
    for (int h = 0; h < 32; ++h) {
        ulonglong2 n0 = row[h * 8 + 4], n1 = row[h * 8 + 5],
                   n2 = row[h * 8 + 6], n3 = row[h * 8 + 7];

        u64 t0 = 0ULL, t1 = 0ULL;
        t0 = ffma2(c0.x, Pp[0], t0);  t1 = ffma2(c0.y, Pp[1], t1);
        t0 = ffma2(c1.x, Pp[2], t0);  t1 = ffma2(c1.y, Pp[3], t1);
        t0 = ffma2(c2.x, Pp[4], t0);  t1 = ffma2(c2.y, Pp[5], t1);
        t0 = ffma2(c3.x, Pp[6], t0);  t1 = ffma2(c3.y, Pp[7], t1);

        if (h < 31) {
            c0 = row[(h + 1) * 8 + 0]; c1 = row[(h + 1) * 8 + 1];
            c2 = row[(h + 1) * 8 + 2]; c3 = row[(h + 1) * 8 + 3];
        }

        t0 = ffma2(n0.x, Pp[8],  t0);  t1 = ffma2(n0.y, Pp[9],  t1);
        t0 = ffma2(n1.x, Pp[10], t0);  t1 = ffma2(n1.y, Pp[11], t1);
        t0 = ffma2(n2.x, Pp[12], t0);  t1 = ffma2(n2.y, Pp[13], t1);
        t0 = ffma2(n3.x, Pp[14], t0);  t1 = ffma2(n3.y, Pp[15], t1);

        u64 v2 = fadd2(t0, t1);   // packed partial pair for g_h

        // streaming binary-counter Horner tree over h (packed form)
        bool done = false;
        #pragma unroll
        for (int p = 0; p < 5; ++p) {
            if (!done) {
                if ((h >> p) & 1) {
                    v2 = ffma2(v2, sHp[p], lvl[p]);
                } else {
                    lvl[p] = v2;
                    done = true;
                }
            }
        }
        if (h == 31) res2 = v2;
    }

    const float res = hsum2(res2);

    // ---- epilogue: Linear(D,1) warp reduce, Linear(L,1), sigmoid ----
    float v = (res + dend_b[l]) * lin_w[l * ND + d];
    #pragma unroll
    for (int off = 16; off; off >>= 1)
        v += __shfl_xor_sync(0xffffffffu, v, off);
    if (d == 0) sred[l] = (v + lin_b[l]) * final_w[l];
    __syncthreads();
    if (tid == 0) {
        float fin = sred[0] + sred[1] + sred[2] + sred[3] + final_b[0];
        out[b] = 1.0f / (1.0f + __expf(-ks[0] * fin));
    }
}

extern "C" void kernel_launch(void* const* d_in, const int* in_sizes, int n_in,
                              void* d_out, int out_size) {
    const float* x       = (const float*)d_in[0];
    const float* k       = (const float*)d_in[1];
    const float* w       = (const float*)d_in[2];
    const float* q       = (const float*)d_in[3];
    const float* dend_w  = (const float*)d_in[4];
    const float* dend_b  = (const float*)d_in[5];
    const float* lin_w   = (const float*)d_in[6];
    const float* lin_b   = (const float*)d_in[7];
    const float* final_w = (const float*)d_in[8];
    const float* final_b = (const float*)d_in[9];
    const float* ks      = (const float*)d_in[10];
    float* out = (float*)d_out;
    dendrite_kernel<<<NB, 128>>>(x, k, w, q, dend_w, dend_b,
                                 lin_w, lin_b, final_w, final_b, ks, out);
}